// round 5
// baseline (speedup 1.0000x reference)
#include <cuda_runtime.h>
#include <math.h>

// Problem constants
#define NROWS 32768        // B*L = 8*4096
#define DD    1024
#define NGC   1024         // global codes
#define NLC   256          // local codes
#define NCC   1280         // NGC+NLC
#define MOM_G 0.999f
#define MOM_L 0.8f
#define TEMP_INV (1.0f/0.07f)
#define EPSN  1e-12f

// ---------------- scratch (device globals; no allocation allowed) ---------------
// Aliasing (stream-serialized live ranges):
//   g_hidden : relu(z@W1+b1)  ->  znorm (after zproj GEMM)  ->  gate (after loss_direct)
//   g_unorm  : l2norm(u)      ->  WU = weights@combined (after loss_direct)
__device__ float g_hidden[NROWS * DD];
__device__ float g_zproj [NROWS * DD];
__device__ float g_unorm [NROWS * DD];
__device__ float g_S     [NROWS * NCC];  // sim / logits / softmax weights
__device__ float g_comb  [NCC * DD];     // updated dicts (global then local)
__device__ float g_sums  [NCC * DD];     // segment sums
__device__ float g_counts[NCC];
__device__ int   g_idx   [2 * NROWS];    // argmax global, argmax local
__device__ double g_loss [3];            // sum|S_g|, sum|S_l|, sum|dot|

// ---------------- reductions ----------------
__device__ __forceinline__ float blk_reduce(float v, int op /*0 sum, 1 max*/) {
    __shared__ float sh[32];
    __syncthreads();  // protect against reuse across calls
    int lane = threadIdx.x & 31, wid = threadIdx.x >> 5;
    #pragma unroll
    for (int o = 16; o > 0; o >>= 1) {
        float w = __shfl_down_sync(0xffffffffu, v, o);
        v = op ? fmaxf(v, w) : v + w;
    }
    if (lane == 0) sh[wid] = v;
    __syncthreads();
    int nw = blockDim.x >> 5;
    v = (threadIdx.x < nw) ? sh[threadIdx.x] : (op ? -1e30f : 0.0f);
    if (wid == 0) {
        #pragma unroll
        for (int o = 16; o > 0; o >>= 1) {
            float w = __shfl_down_sync(0xffffffffu, v, o);
            v = op ? fmaxf(v, w) : v + w;
        }
        if (lane == 0) sh[0] = v;
    }
    __syncthreads();
    return sh[0];
}

// ---------------- GEMM: C[M,N] = A[M,K] @ op(B), row-major ----------------
// BT=0: B is [K,N] row-major (NN).  BT=1: B is [N,K] row-major (NT, i.e. A@B^T).
// act: 0 none, 1 relu, 2 sigmoid. bias may be nullptr.
template<int BT>
__global__ __launch_bounds__(256) void gemm_kernel(
    const float* __restrict__ A, const float* __restrict__ B,
    const float* __restrict__ bias, float* __restrict__ C,
    int M, int N, int K, int ldc, int act)
{
    const int BM = 128, BN = 128, BK = 16;
    __shared__ float As[BK][BM];
    __shared__ float Bs[BK][BN];
    int tid = threadIdx.x;
    int bx = blockIdx.x, by = blockIdx.y;
    const float* Ab = A + (size_t)by * BM * K;

    float acc[8][8];
    #pragma unroll
    for (int i = 0; i < 8; i++)
        #pragma unroll
        for (int j = 0; j < 8; j++) acc[i][j] = 0.0f;

    int ar = tid >> 2, ac = (tid & 3) << 2;    // A tile: 64 rows/pass x 16 cols
    int br = tid >> 5, bc = (tid & 31) << 2;   // B tile (NN): 8 rows/pass x 128 cols

    for (int k0 = 0; k0 < K; k0 += BK) {
        #pragma unroll
        for (int p = 0; p < 2; p++) {
            int r = ar + p * 64;
            float4 v = *(const float4*)(Ab + (size_t)r * K + k0 + ac);
            As[ac + 0][r] = v.x; As[ac + 1][r] = v.y;
            As[ac + 2][r] = v.z; As[ac + 3][r] = v.w;
        }
        if (BT == 0) {
            #pragma unroll
            for (int p = 0; p < 2; p++) {
                int r = br + p * 8;
                float4 v = *(const float4*)(B + (size_t)(k0 + r) * N + bx * BN + bc);
                *(float4*)&Bs[r][bc] = v;
            }
        } else {
            #pragma unroll
            for (int p = 0; p < 2; p++) {
                int cc = ar + p * 64;
                float4 v = *(const float4*)(B + (size_t)(bx * BN + cc) * K + k0 + ac);
                Bs[ac + 0][cc] = v.x; Bs[ac + 1][cc] = v.y;
                Bs[ac + 2][cc] = v.z; Bs[ac + 3][cc] = v.w;
            }
        }
        __syncthreads();

        int ty = tid >> 4, tx = tid & 15;
        #pragma unroll
        for (int kk = 0; kk < BK; kk++) {
            float a[8], b[8];
            *(float4*)&a[0] = *(float4*)&As[kk][ty * 8];
            *(float4*)&a[4] = *(float4*)&As[kk][ty * 8 + 4];
            *(float4*)&b[0] = *(float4*)&Bs[kk][tx * 8];
            *(float4*)&b[4] = *(float4*)&Bs[kk][tx * 8 + 4];
            #pragma unroll
            for (int i = 0; i < 8; i++)
                #pragma unroll
                for (int j = 0; j < 8; j++)
                    acc[i][j] += a[i] * b[j];
        }
        __syncthreads();
    }

    int ty = tid >> 4, tx = tid & 15;
    int row0 = by * BM + ty * 8;
    int col0 = bx * BN + tx * 8;
    #pragma unroll
    for (int i = 0; i < 8; i++) {
        #pragma unroll
        for (int j = 0; j < 8; j++) {
            float v = acc[i][j];
            int col = col0 + j;
            if (bias) v += bias[col];
            if (act == 1) v = v > 0.0f ? v : 0.0f;
            else if (act == 2) v = 1.0f / (1.0f + expf(-v));
            C[(size_t)(row0 + i) * ldc + col] = v;
        }
    }
}

// ---------------- row L2 normalize + optional raw copy to out ----------------
__global__ __launch_bounds__(256) void normalize_rows(const float* __restrict__ in,
                                                      float* __restrict__ out,
                                                      float* __restrict__ raw_copy) {
    int row = blockIdx.x;
    const float* x = in + (size_t)row * DD;
    float s = 0.0f;
    #pragma unroll
    for (int k = threadIdx.x; k < DD; k += 256) { float v = x[k]; s += v * v; }
    float tot = blk_reduce(s, 0);
    float inv = 1.0f / fmaxf(sqrtf(tot), EPSN);
    #pragma unroll
    for (int k = threadIdx.x; k < DD; k += 256) {
        float v = x[k];
        out[(size_t)row * DD + k] = v * inv;
        if (raw_copy) raw_copy[(size_t)row * DD + k] = v;
    }
}

// ---------------- plain copy (dst may be only 4-byte aligned) ----------------
__global__ __launch_bounds__(256) void copy_kernel(const float* __restrict__ src,
                                                   float* __restrict__ dst, size_t n) {
    size_t stride = (size_t)gridDim.x * blockDim.x;
    for (size_t i = (size_t)blockIdx.x * blockDim.x + threadIdx.x; i < n; i += stride)
        dst[i] = src[i];
}

// ---------------- zero scratch accumulators ----------------
__global__ void zero_kernel() {
    int i0 = blockIdx.x * blockDim.x + threadIdx.x;
    int stride = gridDim.x * blockDim.x;
    for (int i = i0; i < NCC * DD; i += stride) g_sums[i] = 0.0f;
    if (i0 < NCC) g_counts[i0] = 0.0f;
    if (i0 < 3) g_loss[i0] = 0.0;
}

// ---------------- argmax over sim rows (first 1024 -> global, last 256 -> local) ----
__global__ __launch_bounds__(256) void argmax_kernel() {
    int row = blockIdx.x;
    const float* s = g_S + (size_t)row * NCC;
    int tid = threadIdx.x;
    __shared__ float sv[256];
    __shared__ int   si[256];

    // global range [0, 1024)
    {
        float best = -1e30f; int bidx = 0;
        for (int c = tid; c < NGC; c += 256) {
            float v = s[c];
            if (v > best) { best = v; bidx = c; }
        }
        sv[tid] = best; si[tid] = bidx;
        __syncthreads();
        for (int off = 128; off > 0; off >>= 1) {
            if (tid < off) {
                if (sv[tid + off] > sv[tid] ||
                    (sv[tid + off] == sv[tid] && si[tid + off] < si[tid])) {
                    sv[tid] = sv[tid + off]; si[tid] = si[tid + off];
                }
            }
            __syncthreads();
        }
        if (tid == 0) g_idx[row] = si[0];
        __syncthreads();
    }
    // local range [1024, 1280)
    {
        float best = -1e30f; int bidx = 0;
        for (int c = tid; c < NLC; c += 256) {
            float v = s[NGC + c];
            if (v > best) { best = v; bidx = c; }
        }
        sv[tid] = best; si[tid] = bidx;
        __syncthreads();
        for (int off = 128; off > 0; off >>= 1) {
            if (tid < off) {
                if (sv[tid + off] > sv[tid] ||
                    (sv[tid + off] == sv[tid] && si[tid + off] < si[tid])) {
                    sv[tid] = sv[tid + off]; si[tid] = si[tid + off];
                }
            }
            __syncthreads();
        }
        if (tid == 0) g_idx[NROWS + row] = si[0];
    }
}

// ---------------- scatter-add segment sums ----------------
__global__ __launch_bounds__(256) void scatter_kernel(const float* __restrict__ unorm) {
    int row = blockIdx.x;
    int cg = g_idx[row];
    int cl = g_idx[NROWS + row] + NGC;
    const float* u = unorm + (size_t)row * DD;
    float* sg = g_sums + (size_t)cg * DD;
    float* sl = g_sums + (size_t)cl * DD;
    for (int k = threadIdx.x; k < DD; k += 256) {
        float v = u[k];
        atomicAdd(&sg[k], v);
        atomicAdd(&sl[k], v);
    }
    if (threadIdx.x == 0) {
        atomicAdd(&g_counts[cg], 1.0f);
        atomicAdd(&g_counts[cl], 1.0f);
    }
}

// ---------------- dict EMA update + renormalize into g_comb ----------------
__global__ __launch_bounds__(256) void dict_update(const float* __restrict__ gdict,
                                                   const float* __restrict__ ldict) {
    int c = blockIdx.x;
    const float* d = (c < NGC) ? (gdict + (size_t)c * DD)
                               : (ldict + (size_t)(c - NGC) * DD);
    float m = (c < NGC) ? MOM_G : MOM_L;
    float cnt = g_counts[c];
    float invc = 1.0f / fmaxf(cnt, 1.0f);
    float vals[4];
    float s = 0.0f;
    #pragma unroll
    for (int i = 0; i < 4; i++) {
        int k = threadIdx.x + i * 256;
        float dv = d[k];
        float up = (cnt > 0.0f) ? (m * dv + (1.0f - m) * g_sums[(size_t)c * DD + k] * invc)
                                : dv;
        vals[i] = up;
        s += up * up;
    }
    float tot = blk_reduce(s, 0);
    float inv = 1.0f / fmaxf(sqrtf(tot), EPSN);
    #pragma unroll
    for (int i = 0; i < 4; i++) {
        int k = threadIdx.x + i * 256;
        g_comb[(size_t)c * DD + k] = vals[i] * inv;
    }
}

// ---------------- |S| sums for loss_g / loss_l ----------------
__global__ __launch_bounds__(256) void loss_abs_kernel() {
    float sg = 0.0f, sl = 0.0f;
    for (int row = blockIdx.x; row < NROWS; row += gridDim.x) {
        const float* s = g_S + (size_t)row * NCC;
        for (int c = threadIdx.x; c < NCC; c += 256) {
            float v = fabsf(s[c]);
            if (c < NGC) sg += v; else sl += v;
        }
    }
    float bg = blk_reduce(sg, 0);
    float bl = blk_reduce(sl, 0);
    if (threadIdx.x == 0) {
        atomicAdd(&g_loss[0], (double)bg);
        atomicAdd(&g_loss[1], (double)bl);
    }
}

// ---------------- |row dot(z_norm, u_norm)| sum for loss_direct ----------------
__global__ __launch_bounds__(256) void loss_direct_kernel(const float* __restrict__ znorm,
                                                          const float* __restrict__ unorm) {
    float part = 0.0f;
    for (int row = blockIdx.x; row < NROWS; row += gridDim.x) {
        const float* zn = znorm + (size_t)row * DD;
        const float* un = unorm + (size_t)row * DD;
        float s = 0.0f;
        #pragma unroll
        for (int k = threadIdx.x; k < DD; k += 256) s += zn[k] * un[k];
        float dot = blk_reduce(s, 0);
        if (threadIdx.x == 0) part += fabsf(dot);
    }
    if (threadIdx.x == 0) atomicAdd(&g_loss[2], (double)part);
}

// ---------------- row softmax of S/TEMP (in place) ----------------
__global__ __launch_bounds__(256) void softmax_kernel() {
    int row = blockIdx.x;
    float* s = g_S + (size_t)row * NCC;
    int tid = threadIdx.x;
    float lv[5];
    float m = -1e30f;
    #pragma unroll
    for (int i = 0; i < 5; i++) { lv[i] = s[tid + i * 256]; m = fmaxf(m, lv[i]); }
    float M = blk_reduce(m, 1);
    float sum = 0.0f;
    #pragma unroll
    for (int i = 0; i < 5; i++) { lv[i] = expf((lv[i] - M) * TEMP_INV); sum += lv[i]; }
    float S = blk_reduce(sum, 0);
    float inv = 1.0f / S;
    #pragma unroll
    for (int i = 0; i < 5; i++) s[tid + i * 256] = lv[i] * inv;
}

// ---------------- z_clean = z - gate * weighted_u ----------------
__global__ __launch_bounds__(256) void final_kernel(const float* __restrict__ z,
                                                    const float* __restrict__ gate,
                                                    const float* __restrict__ wu,
                                                    float* __restrict__ out) {
    size_t stride = (size_t)gridDim.x * blockDim.x;
    for (size_t i = (size_t)blockIdx.x * blockDim.x + threadIdx.x;
         i < (size_t)NROWS * DD; i += stride)
        out[i] = z[i] - gate[i] * wu[i];
}

__global__ void write_loss(float* out_loss) {
    if (threadIdx.x == 0 && blockIdx.x == 0) {
        double l = g_loss[0] / ((double)NROWS * NGC)
                 + g_loss[1] / ((double)NROWS * NLC)
                 + g_loss[2] / (double)NROWS;
        out_loss[0] = (float)l;
    }
}

// ---------------- host launch ----------------
extern "C" void kernel_launch(void* const* d_in, const int* in_sizes, int n_in,
                              void* d_out, int out_size) {
    const float* z     = (const float*)d_in[0];
    const float* u     = (const float*)d_in[1];
    const float* W1    = (const float*)d_in[2];
    const float* b1    = (const float*)d_in[3];
    const float* W2    = (const float*)d_in[4];
    const float* b2    = (const float*)d_in[5];
    const float* Wg    = (const float*)d_in[6];
    const float* bg    = (const float*)d_in[7];
    const float* gdict = (const float*)d_in[8];
    const float* ldict = (const float*)d_in[9];

    float* out        = (float*)d_out;
    float* out_zclean = out;
    float* out_loss   = out + (size_t)NROWS * DD;
    float* out_zproj  = out_loss + 1;
    float* out_u      = out_zproj + (size_t)NROWS * DD;

    float *hidden, *zproj, *unorm, *S, *comb;
    cudaGetSymbolAddress((void**)&hidden, g_hidden);
    cudaGetSymbolAddress((void**)&zproj,  g_zproj);
    cudaGetSymbolAddress((void**)&unorm,  g_unorm);
    cudaGetSymbolAddress((void**)&S,      g_S);
    cudaGetSymbolAddress((void**)&comb,   g_comb);
    float* znorm = hidden;   // alias: hidden's relu output dead after zproj GEMM
    float* wu    = unorm;    // alias: unorm dead after loss_direct
    float* gate  = hidden;   // alias: znorm dead after loss_direct

    zero_kernel<<<1024, 256>>>();

    // normalize u; also emit raw u to output tail
    normalize_rows<<<NROWS, 256>>>(u, unorm, out_u);

    // projector
    gemm_kernel<0><<<dim3(DD / 128, NROWS / 128), 256>>>(z, W1, b1, hidden,
                                                         NROWS, DD, DD, DD, 1);
    gemm_kernel<0><<<dim3(DD / 128, NROWS / 128), 256>>>(hidden, W2, b2, zproj,
                                                         NROWS, DD, DD, DD, 0);
    copy_kernel<<<2048, 256>>>(zproj, out_zproj, (size_t)NROWS * DD);
    // znorm overwrites hidden (relu output no longer needed)
    normalize_rows<<<NROWS, 256>>>(zproj, znorm, nullptr);

    // sim against OLD dicts -> S, then assignments + dict updates
    gemm_kernel<1><<<dim3(NGC / 128, NROWS / 128), 256>>>(unorm, gdict, nullptr, S,
                                                          NROWS, NGC, DD, NCC, 0);
    gemm_kernel<1><<<dim3(NLC / 128, NROWS / 128), 256>>>(unorm, ldict, nullptr, S + NGC,
                                                          NROWS, NLC, DD, NCC, 0);
    argmax_kernel<<<NROWS, 256>>>();
    scatter_kernel<<<NROWS, 256>>>(unorm);
    dict_update<<<NCC, 256>>>(gdict, ldict);

    // logits against UPDATED dicts -> S; losses; softmax; weighted_u
    gemm_kernel<1><<<dim3(NCC / 128, NROWS / 128), 256>>>(znorm, comb, nullptr, S,
                                                          NROWS, NCC, DD, NCC, 0);
    loss_abs_kernel<<<1024, 256>>>();
    loss_direct_kernel<<<1024, 256>>>(znorm, unorm);
    softmax_kernel<<<NROWS, 256>>>();
    // wu overwrites unorm (dead after loss_direct)
    gemm_kernel<0><<<dim3(DD / 128, NROWS / 128), 256>>>(S, comb, nullptr, wu,
                                                         NROWS, DD, NCC, DD, 0);

    // gate overwrites hidden/znorm (dead after loss_direct)
    gemm_kernel<0><<<dim3(DD / 128, NROWS / 128), 256>>>(zproj, Wg, bg, gate,
                                                         NROWS, DD, DD, DD, 2);
    final_kernel<<<2048, 256>>>(z, gate, wu, out_zclean);
    write_loss<<<1, 32>>>(out_loss);
}

// round 7
// speedup vs baseline: 1.8765x; 1.8765x over previous
#include <cuda_runtime.h>
#include <cstdint>
#include <math.h>

// Problem constants
#define NROWS 32768        // B*L = 8*4096
#define DD    1024
#define NGC   1024
#define NLC   256
#define NCC   1280
#define MOM_G 0.999f
#define MOM_L 0.8f
#define TEMP_INV (1.0f/0.07f)
#define EPSN  1e-12f

// ================= scratch (device globals) =================
__device__ float g_hidden[NROWS * DD];   // relu -> znorm -> gate
__device__ float g_zproj [NROWS * DD];
__device__ float g_unorm [NROWS * DD];   // unorm -> wu
__device__ float g_S     [NROWS * NCC];
__device__ float g_comb  [NCC * DD];
__device__ float g_sums  [NCC * DD];     // sums -> combT
__device__ float g_Wt    [DD * DD];
__device__ float g_counts[NCC];
__device__ int   g_idx   [2 * NROWS];
__device__ double g_loss [3];

// ================= tf32 mma.sync GEMM =================
__device__ __forceinline__ uint32_t tf32_rn(float a) {
    uint32_t b; asm("cvt.rna.tf32.f32 %0, %1;" : "=r"(b) : "f"(a));
    return b;
}
__device__ __forceinline__ void mma_tf32(float c[4], uint32_t a0, uint32_t a1,
                                         uint32_t a2, uint32_t a3,
                                         uint32_t b0, uint32_t b1) {
    asm volatile("mma.sync.aligned.m16n8k8.row.col.f32.tf32.tf32.f32 "
        "{%0,%1,%2,%3}, {%4,%5,%6,%7}, {%8,%9}, {%0,%1,%2,%3};"
        : "+f"(c[0]), "+f"(c[1]), "+f"(c[2]), "+f"(c[3])
        : "r"(a0), "r"(a1), "r"(a2), "r"(a3), "r"(b0), "r"(b1));
}
#define CP16(dst_u32, src_ptr) \
    asm volatile("cp.async.cg.shared.global [%0], [%1], 16;" :: "r"(dst_u32), "l"(src_ptr))
#define CP_COMMIT() asm volatile("cp.async.commit_group;" ::: "memory")
#define CP_WAIT1()  asm volatile("cp.async.wait_group 1;" ::: "memory")
#define CP_WAIT0()  asm volatile("cp.async.wait_group 0;" ::: "memory")

#define TPAD 36   // floats per SMEM row (32 data + 4 pad); frag LDS bank == lane

// C[M,N] = A[M,K] @ B[N,K]^T, all row-major. CTA 128x128, warp 64x32, BK=32.
// SPLIT=1: 3xTF32 (fp32-accurate). ACT: 0 none, 1 relu, 2 sigmoid.
template<int SPLIT, int ACT>
__global__ __launch_bounds__(256) void tgemm(
    const float* __restrict__ A, const float* __restrict__ B,
    const float* __restrict__ bias, float* __restrict__ C,
    int N, int K, int ldc)
{
    extern __shared__ float sm[];
    float* As = sm;                    // [2][128][TPAD]
    float* Bs = sm + 2 * 128 * TPAD;   // [2][128][TPAD]
    const int tid = threadIdx.x;
    const int lane = tid & 31, wid = tid >> 5;
    const int wm = wid >> 2, wn = wid & 3;
    const int m0 = blockIdx.y * 128, n0 = blockIdx.x * 128;
    const uint32_t s_as = (uint32_t)__cvta_generic_to_shared(As);
    const uint32_t s_bs = (uint32_t)__cvta_generic_to_shared(Bs);
    const float* gA = A + (size_t)m0 * K;
    const float* gB = B + (size_t)n0 * K;
    const int NK = K / 32;

    float acc[4][4][4];
    #pragma unroll
    for (int i = 0; i < 4; i++)
        #pragma unroll
        for (int j = 0; j < 4; j++)
            #pragma unroll
            for (int q = 0; q < 4; q++) acc[i][j][q] = 0.0f;

    // ---- async tile loader: 128 rows x 32 floats each for A and B ----
    const int lr = tid >> 1;           // row 0..127
    const int lc = (tid & 1) << 4;     // col 0 or 16 (4 float4 each)
    #define LOAD_TILE(kt, buf) do { \
        const float* asrc = gA + (size_t)lr * K + (kt) * 32 + lc; \
        const float* bsrc = gB + (size_t)lr * K + (kt) * 32 + lc; \
        uint32_t ad = s_as + (((buf) * 128 + lr) * TPAD + lc) * 4; \
        uint32_t bd = s_bs + (((buf) * 128 + lr) * TPAD + lc) * 4; \
        CP16(ad, asrc);      CP16(ad + 16, asrc + 4); \
        CP16(ad + 32, asrc + 8); CP16(ad + 48, asrc + 12); \
        CP16(bd, bsrc);      CP16(bd + 16, bsrc + 4); \
        CP16(bd + 32, bsrc + 8); CP16(bd + 48, bsrc + 12); \
    } while (0)

    LOAD_TILE(0, 0);
    CP_COMMIT();

    for (int kt = 0; kt < NK; kt++) {
        const int buf = kt & 1;
        if (kt + 1 < NK) { LOAD_TILE(kt + 1, (kt + 1) & 1); CP_COMMIT(); CP_WAIT1(); }
        else             { CP_WAIT0(); }
        __syncthreads();

        #pragma unroll
        for (int ks = 0; ks < 4; ks++) {
            const int k = ks * 8 + (lane & 3);
            uint32_t ah[4][4], al[4][4], bh[4][2], bl[4][2];
            #pragma unroll
            for (int mi = 0; mi < 4; mi++) {
                int row = wm * 64 + mi * 16 + (lane >> 2);
                const float* r0 = &As[(buf * 128 + row) * TPAD];
                const float* r1 = r0 + 8 * TPAD;
                float v0 = r0[k], v1 = r1[k], v2 = r0[k + 4], v3 = r1[k + 4];
                ah[mi][0] = tf32_rn(v0); ah[mi][1] = tf32_rn(v1);
                ah[mi][2] = tf32_rn(v2); ah[mi][3] = tf32_rn(v3);
                if (SPLIT) {
                    al[mi][0] = tf32_rn(v0 - __uint_as_float(ah[mi][0]));
                    al[mi][1] = tf32_rn(v1 - __uint_as_float(ah[mi][1]));
                    al[mi][2] = tf32_rn(v2 - __uint_as_float(ah[mi][2]));
                    al[mi][3] = tf32_rn(v3 - __uint_as_float(ah[mi][3]));
                }
            }
            #pragma unroll
            for (int ni = 0; ni < 4; ni++) {
                int n = wn * 32 + ni * 8 + (lane >> 2);
                const float* r0 = &Bs[(buf * 128 + n) * TPAD];
                float w0 = r0[k], w1 = r0[k + 4];
                bh[ni][0] = tf32_rn(w0); bh[ni][1] = tf32_rn(w1);
                if (SPLIT) {
                    bl[ni][0] = tf32_rn(w0 - __uint_as_float(bh[ni][0]));
                    bl[ni][1] = tf32_rn(w1 - __uint_as_float(bh[ni][1]));
                }
            }
            #pragma unroll
            for (int mi = 0; mi < 4; mi++)
                #pragma unroll
                for (int ni = 0; ni < 4; ni++) {
                    if (SPLIT) {
                        mma_tf32(acc[mi][ni], al[mi][0], al[mi][1], al[mi][2], al[mi][3],
                                 bh[ni][0], bh[ni][1]);
                        mma_tf32(acc[mi][ni], ah[mi][0], ah[mi][1], ah[mi][2], ah[mi][3],
                                 bl[ni][0], bl[ni][1]);
                    }
                    mma_tf32(acc[mi][ni], ah[mi][0], ah[mi][1], ah[mi][2], ah[mi][3],
                             bh[ni][0], bh[ni][1]);
                }
        }
        __syncthreads();
    }

    // ---- epilogue ----
    #pragma unroll
    for (int mi = 0; mi < 4; mi++) {
        #pragma unroll
        for (int ni = 0; ni < 4; ni++) {
            int row = m0 + wm * 64 + mi * 16 + (lane >> 2);
            int col = n0 + wn * 32 + ni * 8 + 2 * (lane & 3);
            float b0 = 0.f, b1 = 0.f;
            if (bias) { b0 = bias[col]; b1 = bias[col + 1]; }
            #pragma unroll
            for (int h = 0; h < 2; h++) {
                float v0 = acc[mi][ni][2 * h + 0] + b0;
                float v1 = acc[mi][ni][2 * h + 1] + b1;
                if (ACT == 1) { v0 = fmaxf(v0, 0.f); v1 = fmaxf(v1, 0.f); }
                else if (ACT == 2) {
                    v0 = 1.0f / (1.0f + expf(-v0));
                    v1 = 1.0f / (1.0f + expf(-v1));
                }
                float2 p = make_float2(v0, v1);
                *(float2*)&C[(size_t)(row + 8 * h) * ldc + col] = p;
            }
        }
    }
}

// ================= transpose: out[C][R] = in[R][C] =================
__global__ void transpose_kernel(const float* __restrict__ in, float* __restrict__ out,
                                 int R, int C) {
    __shared__ float t[32][33];
    int c = blockIdx.x * 32 + threadIdx.x;
    int r0 = blockIdx.y * 32;
    for (int dy = threadIdx.y; dy < 32; dy += 8)
        t[dy][threadIdx.x] = in[(size_t)(r0 + dy) * C + c];
    __syncthreads();
    int rr = r0 + threadIdx.x;
    int cc0 = blockIdx.x * 32;
    for (int dy = threadIdx.y; dy < 32; dy += 8)
        out[(size_t)(cc0 + dy) * R + rr] = t[threadIdx.x][dy];
}

// ================= small kernels =================
__device__ __forceinline__ float blk_reduce(float v, int op) {
    __shared__ float sh[32];
    __syncthreads();
    int lane = threadIdx.x & 31, wid = threadIdx.x >> 5;
    #pragma unroll
    for (int o = 16; o > 0; o >>= 1) {
        float w = __shfl_down_sync(0xffffffffu, v, o);
        v = op ? fmaxf(v, w) : v + w;
    }
    if (lane == 0) sh[wid] = v;
    __syncthreads();
    int nw = blockDim.x >> 5;
    v = (threadIdx.x < nw) ? sh[threadIdx.x] : (op ? -1e30f : 0.0f);
    if (wid == 0) {
        #pragma unroll
        for (int o = 16; o > 0; o >>= 1) {
            float w = __shfl_down_sync(0xffffffffu, v, o);
            v = op ? fmaxf(v, w) : v + w;
        }
        if (lane == 0) sh[0] = v;
    }
    __syncthreads();
    return sh[0];
}

__global__ __launch_bounds__(256) void normalize_rows(const float* __restrict__ in,
                                                      float* __restrict__ out,
                                                      float* __restrict__ raw_copy) {
    int row = blockIdx.x;
    const float* x = in + (size_t)row * DD;
    float s = 0.0f;
    #pragma unroll
    for (int k = threadIdx.x; k < DD; k += 256) { float v = x[k]; s += v * v; }
    float tot = blk_reduce(s, 0);
    float inv = 1.0f / fmaxf(sqrtf(tot), EPSN);
    #pragma unroll
    for (int k = threadIdx.x; k < DD; k += 256) {
        float v = x[k];
        out[(size_t)row * DD + k] = v * inv;
        if (raw_copy) raw_copy[(size_t)row * DD + k] = v;
    }
}

__global__ __launch_bounds__(256) void copy_kernel(const float* __restrict__ src,
                                                   float* __restrict__ dst, size_t n) {
    size_t stride = (size_t)gridDim.x * blockDim.x;
    for (size_t i = (size_t)blockIdx.x * blockDim.x + threadIdx.x; i < n; i += stride)
        dst[i] = src[i];
}

__global__ void zero_kernel() {
    int i0 = blockIdx.x * blockDim.x + threadIdx.x;
    int stride = gridDim.x * blockDim.x;
    for (int i = i0; i < NCC * DD; i += stride) g_sums[i] = 0.0f;
    if (i0 < NCC) g_counts[i0] = 0.0f;
    if (i0 < 3) g_loss[i0] = 0.0;
}

__global__ __launch_bounds__(256) void argmax_kernel() {
    int row = blockIdx.x;
    const float* s = g_S + (size_t)row * NCC;
    int tid = threadIdx.x;
    __shared__ float sv[256];
    __shared__ int   si[256];
    {
        float best = -1e30f; int bidx = 0;
        for (int c = tid; c < NGC; c += 256) {
            float v = s[c];
            if (v > best) { best = v; bidx = c; }
        }
        sv[tid] = best; si[tid] = bidx;
        __syncthreads();
        for (int off = 128; off > 0; off >>= 1) {
            if (tid < off) {
                if (sv[tid + off] > sv[tid] ||
                    (sv[tid + off] == sv[tid] && si[tid + off] < si[tid])) {
                    sv[tid] = sv[tid + off]; si[tid] = si[tid + off];
                }
            }
            __syncthreads();
        }
        if (tid == 0) g_idx[row] = si[0];
        __syncthreads();
    }
    {
        float best = -1e30f; int bidx = 0;
        for (int c = tid; c < NLC; c += 256) {
            float v = s[NGC + c];
            if (v > best) { best = v; bidx = c; }
        }
        sv[tid] = best; si[tid] = bidx;
        __syncthreads();
        for (int off = 128; off > 0; off >>= 1) {
            if (tid < off) {
                if (sv[tid + off] > sv[tid] ||
                    (sv[tid + off] == sv[tid] && si[tid + off] < si[tid])) {
                    sv[tid] = sv[tid + off]; si[tid] = si[tid + off];
                }
            }
            __syncthreads();
        }
        if (tid == 0) g_idx[NROWS + row] = si[0];
    }
}

__global__ __launch_bounds__(256) void scatter_kernel(const float* __restrict__ unorm) {
    int row = blockIdx.x;
    int cg = g_idx[row];
    int cl = g_idx[NROWS + row] + NGC;
    const float* u = unorm + (size_t)row * DD;
    float* sg = g_sums + (size_t)cg * DD;
    float* sl = g_sums + (size_t)cl * DD;
    for (int k = threadIdx.x; k < DD; k += 256) {
        float v = u[k];
        atomicAdd(&sg[k], v);
        atomicAdd(&sl[k], v);
    }
    if (threadIdx.x == 0) {
        atomicAdd(&g_counts[cg], 1.0f);
        atomicAdd(&g_counts[cl], 1.0f);
    }
}

__global__ __launch_bounds__(256) void dict_update(const float* __restrict__ gdict,
                                                   const float* __restrict__ ldict) {
    int c = blockIdx.x;
    const float* d = (c < NGC) ? (gdict + (size_t)c * DD)
                               : (ldict + (size_t)(c - NGC) * DD);
    float m = (c < NGC) ? MOM_G : MOM_L;
    float cnt = g_counts[c];
    float invc = 1.0f / fmaxf(cnt, 1.0f);
    float vals[4];
    float s = 0.0f;
    #pragma unroll
    for (int i = 0; i < 4; i++) {
        int k = threadIdx.x + i * 256;
        float dv = d[k];
        float up = (cnt > 0.0f) ? (m * dv + (1.0f - m) * g_sums[(size_t)c * DD + k] * invc)
                                : dv;
        vals[i] = up;
        s += up * up;
    }
    float tot = blk_reduce(s, 0);
    float inv = 1.0f / fmaxf(sqrtf(tot), EPSN);
    #pragma unroll
    for (int i = 0; i < 4; i++) {
        int k = threadIdx.x + i * 256;
        g_comb[(size_t)c * DD + k] = vals[i] * inv;
    }
}

__global__ __launch_bounds__(256) void loss_abs_kernel() {
    float sg = 0.0f, sl = 0.0f;
    for (int row = blockIdx.x; row < NROWS; row += gridDim.x) {
        const float* s = g_S + (size_t)row * NCC;
        for (int c = threadIdx.x; c < NCC; c += 256) {
            float v = fabsf(s[c]);
            if (c < NGC) sg += v; else sl += v;
        }
    }
    float bg = blk_reduce(sg, 0);
    float bl = blk_reduce(sl, 0);
    if (threadIdx.x == 0) {
        atomicAdd(&g_loss[0], (double)bg);
        atomicAdd(&g_loss[1], (double)bl);
    }
}

__global__ __launch_bounds__(256) void loss_direct_kernel(const float* __restrict__ znorm,
                                                          const float* __restrict__ unorm) {
    float part = 0.0f;
    for (int row = blockIdx.x; row < NROWS; row += gridDim.x) {
        const float* zn = znorm + (size_t)row * DD;
        const float* un = unorm + (size_t)row * DD;
        float s = 0.0f;
        #pragma unroll
        for (int k = threadIdx.x; k < DD; k += 256) s += zn[k] * un[k];
        float dot = blk_reduce(s, 0);
        if (threadIdx.x == 0) part += fabsf(dot);
    }
    if (threadIdx.x == 0) atomicAdd(&g_loss[2], (double)part);
}

__global__ __launch_bounds__(256) void softmax_kernel() {
    int row = blockIdx.x;
    float* s = g_S + (size_t)row * NCC;
    int tid = threadIdx.x;
    float lv[5];
    float m = -1e30f;
    #pragma unroll
    for (int i = 0; i < 5; i++) { lv[i] = s[tid + i * 256]; m = fmaxf(m, lv[i]); }
    float M = blk_reduce(m, 1);
    float sum = 0.0f;
    #pragma unroll
    for (int i = 0; i < 5; i++) { lv[i] = expf((lv[i] - M) * TEMP_INV); sum += lv[i]; }
    float S = blk_reduce(sum, 0);
    float inv = 1.0f / S;
    #pragma unroll
    for (int i = 0; i < 5; i++) s[tid + i * 256] = lv[i] * inv;
}

__global__ __launch_bounds__(256) void final_kernel(const float* __restrict__ z,
                                                    const float* __restrict__ gate,
                                                    const float* __restrict__ wu,
                                                    float* __restrict__ out) {
    size_t stride = (size_t)gridDim.x * blockDim.x;
    for (size_t i = (size_t)blockIdx.x * blockDim.x + threadIdx.x;
         i < (size_t)NROWS * DD; i += stride)
        out[i] = z[i] - gate[i] * wu[i];
}

__global__ void write_loss(float* out_loss) {
    if (threadIdx.x == 0 && blockIdx.x == 0) {
        double l = g_loss[0] / ((double)NROWS * NGC)
                 + g_loss[1] / ((double)NROWS * NLC)
                 + g_loss[2] / (double)NROWS;
        out_loss[0] = (float)l;
    }
}

// ================= host launch =================
extern "C" void kernel_launch(void* const* d_in, const int* in_sizes, int n_in,
                              void* d_out, int out_size) {
    const float* z     = (const float*)d_in[0];
    const float* u     = (const float*)d_in[1];
    const float* W1    = (const float*)d_in[2];
    const float* b1    = (const float*)d_in[3];
    const float* W2    = (const float*)d_in[4];
    const float* b2    = (const float*)d_in[5];
    const float* Wg    = (const float*)d_in[6];
    const float* bg    = (const float*)d_in[7];
    const float* gdict = (const float*)d_in[8];
    const float* ldict = (const float*)d_in[9];

    float* out        = (float*)d_out;
    float* out_zclean = out;
    float* out_loss   = out + (size_t)NROWS * DD;
    float* out_zproj  = out_loss + 1;
    float* out_u      = out_zproj + (size_t)NROWS * DD;

    float *hidden, *zproj, *unorm, *S, *comb, *sums, *Wt;
    cudaGetSymbolAddress((void**)&hidden, g_hidden);
    cudaGetSymbolAddress((void**)&zproj,  g_zproj);
    cudaGetSymbolAddress((void**)&unorm,  g_unorm);
    cudaGetSymbolAddress((void**)&S,      g_S);
    cudaGetSymbolAddress((void**)&comb,   g_comb);
    cudaGetSymbolAddress((void**)&sums,   g_sums);
    cudaGetSymbolAddress((void**)&Wt,     g_Wt);
    float* znorm = hidden;   // relu output dead after proj2
    float* wu    = unorm;    // unorm dead after loss_direct
    float* gate  = hidden;   // znorm dead after loss_direct
    float* combT = sums;     // sums dead after dict_update

    const int SMEM = 2 * 2 * 128 * TPAD * 4;   // 73728 B
    cudaFuncSetAttribute(tgemm<0,0>, cudaFuncAttributeMaxDynamicSharedMemorySize, SMEM);
    cudaFuncSetAttribute(tgemm<0,2>, cudaFuncAttributeMaxDynamicSharedMemorySize, SMEM);
    cudaFuncSetAttribute(tgemm<1,0>, cudaFuncAttributeMaxDynamicSharedMemorySize, SMEM);
    cudaFuncSetAttribute(tgemm<1,1>, cudaFuncAttributeMaxDynamicSharedMemorySize, SMEM);

    const dim3 TB(32, 8);
    const int MT = NROWS / 128;   // 256 M-tiles

    zero_kernel<<<1024, 256>>>();
    normalize_rows<<<NROWS, 256>>>(u, unorm, out_u);

    // projector (3xTF32 split: z_proj is a direct output)
    transpose_kernel<<<dim3(DD / 32, DD / 32), TB>>>(W1, Wt, DD, DD);
    tgemm<1,1><<<dim3(DD / 128, MT), 256, SMEM>>>(z, Wt, b1, hidden, DD, DD, DD);
    transpose_kernel<<<dim3(DD / 32, DD / 32), TB>>>(W2, Wt, DD, DD);
    tgemm<1,0><<<dim3(DD / 128, MT), 256, SMEM>>>(hidden, Wt, b2, zproj, DD, DD, DD);
    copy_kernel<<<2048, 256>>>(zproj, out_zproj, (size_t)NROWS * DD);
    normalize_rows<<<NROWS, 256>>>(zproj, znorm, nullptr);

    // sim vs OLD dicts (single-pass tf32; consumer argmax)
    tgemm<0,0><<<dim3(NGC / 128, MT), 256, SMEM>>>(unorm, gdict, nullptr, S, NGC, DD, NCC);
    tgemm<0,0><<<dim3(NLC / 128, MT), 256, SMEM>>>(unorm, ldict, nullptr, S + NGC, NLC, DD, NCC);
    argmax_kernel<<<NROWS, 256>>>();
    scatter_kernel<<<NROWS, 256>>>(unorm);
    dict_update<<<NCC, 256>>>(gdict, ldict);

    // logits vs UPDATED dicts -> losses -> softmax -> weighted_u
    tgemm<0,0><<<dim3(NCC / 128, MT), 256, SMEM>>>(znorm, comb, nullptr, S, NCC, DD, NCC);
    loss_abs_kernel<<<1024, 256>>>();
    loss_direct_kernel<<<1024, 256>>>(znorm, unorm);
    softmax_kernel<<<NROWS, 256>>>();
    transpose_kernel<<<dim3(DD / 32, NCC / 32), TB>>>(comb, combT, NCC, DD);
    tgemm<0,0><<<dim3(DD / 128, MT), 256, SMEM>>>(S, combT, nullptr, wu, DD, NCC, DD);

    // gate + final combine
    transpose_kernel<<<dim3(DD / 32, DD / 32), TB>>>(Wg, Wt, DD, DD);
    tgemm<0,2><<<dim3(DD / 128, MT), 256, SMEM>>>(zproj, Wt, bg, gate, DD, DD, DD);
    final_kernel<<<2048, 256>>>(z, gate, wu, out_zclean);
    write_loss<<<1, 32>>>(out_loss);
}